// round 4
// baseline (speedup 1.0000x reference)
#include <cuda_runtime.h>
#include <cuda_bf16.h>
#include <math.h>

#define NN 15840        // nodes
#define EE 253440       // edges
#define BB 48           // graphs
#define HID 256
#define INCH 128

// ---------------- scratch ----------------
__device__ unsigned g_xt[NN * INCH];       // LayerNormed x, tf32 bits
__device__ unsigned g_wt[1024 * INCH];     // packed Wq|Wk|Wv|Wskip, tf32 bits
__device__ float g_bias[1024];
__device__ float g_q[NN * HID];
__device__ float g_k[NN * HID];
__device__ float g_v[NN * HID];
__device__ float g_skip[NN * HID];
__device__ float g_out[NN * HID];
__device__ int   g_cnt[NN];
__device__ int   g_cur[NN];
__device__ int   g_ofs[NN + 1];
__device__ int   g_ssrc[EE];
__device__ int   g_seid[EE];
__device__ float g_bnsum[HID];
__device__ float g_bnsumsq[HID];
__device__ float g_pool[BB * 18 * HID];
__device__ float g_bacc[BB];

__device__ __forceinline__ unsigned f2tf(float f) {
    unsigned r;
    asm("cvt.rna.tf32.f32 %0, %1;" : "=r"(r) : "f"(f));
    return r;
}

// ---------------- init ----------------
__global__ void k_init() {
    int i = blockIdx.x * blockDim.x + threadIdx.x;
    int stride = gridDim.x * blockDim.x;
    for (int t = i; t < NN; t += stride) { g_cnt[t] = 0; g_cur[t] = 0; }
    if (i < HID) { g_bnsum[i] = 0.f; g_bnsumsq[i] = 0.f; }
    if (i < BB) g_bacc[i] = 0.f;
}

// ---------------- CSR build ----------------
__global__ __launch_bounds__(256) void k_count(const int* __restrict__ ei) {
    int e = blockIdx.x * 256 + threadIdx.x;
    if (e < EE) atomicAdd(&g_cnt[ei[EE + e]], 1);
}

__global__ __launch_bounds__(1024) void k_scan() {
    __shared__ int warpsum[32];
    int t = threadIdx.x;
    int base = t * 16;
    int loc[16];
    int s = 0;
    #pragma unroll
    for (int i = 0; i < 16; i++) {
        int idx = base + i;
        int c = (idx < NN) ? g_cnt[idx] : 0;
        loc[i] = s; s += c;
    }
    int lane = t & 31, wid = t >> 5;
    int v = s;
    #pragma unroll
    for (int o = 1; o < 32; o <<= 1) {
        int n = __shfl_up_sync(~0u, v, o);
        if (lane >= o) v += n;
    }
    if (lane == 31) warpsum[wid] = v;
    __syncthreads();
    if (wid == 0) {
        int w = warpsum[lane];
        #pragma unroll
        for (int o = 1; o < 32; o <<= 1) {
            int n = __shfl_up_sync(~0u, w, o);
            if (lane >= o) w += n;
        }
        warpsum[lane] = w;
    }
    __syncthreads();
    int offset = (v - s) + (wid ? warpsum[wid - 1] : 0);
    #pragma unroll
    for (int i = 0; i < 16; i++) {
        int idx = base + i;
        if (idx < NN) g_ofs[idx] = offset + loc[i];
    }
    if (t == 1023) g_ofs[NN] = offset + s;
}

__global__ __launch_bounds__(256) void k_fill(const int* __restrict__ ei) {
    int e = blockIdx.x * 256 + threadIdx.x;
    if (e >= EE) return;
    int d = ei[EE + e];
    int pos = atomicAdd(&g_cur[d], 1);
    int slot = g_ofs[d] + pos;
    g_ssrc[slot] = ei[e];
    g_seid[slot] = e;
}

// ---------------- LayerNorm over 128 features -> tf32 ----------------
__global__ __launch_bounds__(128) void k_ln(const float* __restrict__ x,
                                            const float* __restrict__ lg,
                                            const float* __restrict__ lb) {
    int row = blockIdx.x;
    int c = threadIdx.x;
    float v = x[row * INCH + c];
    __shared__ float sm[4];
    float s = v;
    #pragma unroll
    for (int o = 16; o; o >>= 1) s += __shfl_xor_sync(~0u, s, o);
    int wid = c >> 5, lane = c & 31;
    if (lane == 0) sm[wid] = s;
    __syncthreads();
    float mean = (sm[0] + sm[1] + sm[2] + sm[3]) * (1.f / 128.f);
    float d = v - mean;
    float s2 = d * d;
    #pragma unroll
    for (int o = 16; o; o >>= 1) s2 += __shfl_xor_sync(~0u, s2, o);
    __syncthreads();
    if (lane == 0) sm[wid] = s2;
    __syncthreads();
    float var = (sm[0] + sm[1] + sm[2] + sm[3]) * (1.f / 128.f);
    g_xt[row * INCH + c] = f2tf(d * rsqrtf(var + 1e-5f) * lg[c] + lb[c]);
}

// ---------------- pack weights+bias to tf32 ----------------
__global__ __launch_bounds__(256) void k_conv(const float* __restrict__ Wq, const float* __restrict__ bq,
                                              const float* __restrict__ Wk, const float* __restrict__ bk,
                                              const float* __restrict__ Wv, const float* __restrict__ bv,
                                              const float* __restrict__ Ws, const float* __restrict__ bs) {
    int i = blockIdx.x * 256 + threadIdx.x;
    if (i < 1024 * INCH) {
        int row = i >> 7;
        int g = row >> 8, lr = row & 255, k = i & 127;
        const float* W = (g == 0) ? Wq : (g == 1) ? Wk : (g == 2) ? Wv : Ws;
        g_wt[i] = f2tf(W[lr * INCH + k]);
    }
    if (i < 1024) {
        int g = i >> 8, lr = i & 255;
        const float* b = (g == 0) ? bq : (g == 1) ? bk : (g == 2) ? bv : bs;
        g_bias[i] = b[lr];
    }
}

// ---------------- tf32 tensor-core GEMM: g_xt[N,128] @ g_wt^T -> {q,k,v,skip} ----------------
// 128 threads (4 warps). Block tile M=64, N=128 (warp: M64 x N32), K=128 in one pass.
// A from smem (conflict-free), B fragments straight from L2.
__global__ __launch_bounds__(128) void k_gemm(int dummy) {
    __shared__ unsigned As[64][132];
    int m0  = blockIdx.y * 64;
    int bn0 = blockIdx.x * 128;          // 0..896
    int g = bn0 >> 8;
    float* out = (g == 0) ? g_q : (g == 1) ? g_k : (g == 2) ? g_v : g_skip;
    int lc0 = bn0 & 255;                 // 0 or 128

    int tid = threadIdx.x, lane = tid & 31, warp = tid >> 5;

    // fill A tile (64 x 128), zero-pad past NN
    {
        const uint4* src = (const uint4*)(g_xt + (size_t)m0 * INCH);
        #pragma unroll
        for (int it = 0; it < 16; it++) {
            int u4 = tid + it * 128;          // 0..2047 (32 uint4 per row)
            int r = u4 >> 5, c4 = u4 & 31;
            uint4 v = (m0 + r < NN) ? src[u4] : make_uint4(0u, 0u, 0u, 0u);
            unsigned* dst = &As[r][c4 * 4];
            dst[0] = v.x; dst[1] = v.y; dst[2] = v.z; dst[3] = v.w;
        }
    }
    __syncthreads();

    float acc[4][4][4];
    #pragma unroll
    for (int mi = 0; mi < 4; mi++)
        #pragma unroll
        for (int ni = 0; ni < 4; ni++)
            #pragma unroll
            for (int r = 0; r < 4; r++) acc[mi][ni][r] = 0.f;

    int n0 = bn0 + warp * 32;
    const unsigned* bp[4];
    #pragma unroll
    for (int ni = 0; ni < 4; ni++)
        bp[ni] = g_wt + (size_t)(n0 + ni * 8 + (lane >> 2)) * INCH + (lane & 3);

    int ar = lane >> 2, ac = lane & 3;
    #pragma unroll 4
    for (int ks = 0; ks < 16; ks++) {
        int kk = ks * 8;
        unsigned b0[4], b1[4];
        #pragma unroll
        for (int ni = 0; ni < 4; ni++) { b0[ni] = bp[ni][kk]; b1[ni] = bp[ni][kk + 4]; }
        #pragma unroll
        for (int mi = 0; mi < 4; mi++) {
            int r = mi * 16 + ar;
            unsigned a0 = As[r][kk + ac];
            unsigned a1 = As[r + 8][kk + ac];
            unsigned a2 = As[r][kk + ac + 4];
            unsigned a3 = As[r + 8][kk + ac + 4];
            #pragma unroll
            for (int ni = 0; ni < 4; ni++) {
                asm volatile(
                    "mma.sync.aligned.m16n8k8.row.col.f32.tf32.tf32.f32 "
                    "{%0,%1,%2,%3}, {%4,%5,%6,%7}, {%8,%9}, {%0,%1,%2,%3};"
                    : "+f"(acc[mi][ni][0]), "+f"(acc[mi][ni][1]),
                      "+f"(acc[mi][ni][2]), "+f"(acc[mi][ni][3])
                    : "r"(a0), "r"(a1), "r"(a2), "r"(a3),
                      "r"(b0[ni]), "r"(b1[ni]));
            }
        }
    }

    // epilogue: + bias, guarded stores
    #pragma unroll
    for (int ni = 0; ni < 4; ni++) {
        int gcol = bn0 + warp * 32 + ni * 8 + 2 * (lane & 3);
        int col  = lc0 + warp * 32 + ni * 8 + 2 * (lane & 3);
        float bb0 = g_bias[gcol], bb1 = g_bias[gcol + 1];
        #pragma unroll
        for (int mi = 0; mi < 4; mi++) {
            int row = m0 + mi * 16 + (lane >> 2);
            if (row < NN)
                *(float2*)(out + (size_t)row * HID + col) =
                    make_float2(acc[mi][ni][0] + bb0, acc[mi][ni][1] + bb1);
            if (row + 8 < NN)
                *(float2*)(out + (size_t)(row + 8) * HID + col) =
                    make_float2(acc[mi][ni][2] + bb0, acc[mi][ni][3] + bb1);
        }
    }
}

// ---------------- fused attention: online softmax gather per node ----------------
__global__ __launch_bounds__(256) void k_agg(const float* __restrict__ ea,
                                             const float* __restrict__ We) {
    __shared__ float sWe[HID * 5];
    for (int t = threadIdx.x; t < HID * 5; t += 256) sWe[t] = We[t];
    __syncthreads();
    int node = blockIdx.x * 8 + (threadIdx.x >> 5);
    if (node >= NN) return;
    int lane = threadIdx.x & 31;
    int c0 = lane * 8;
    int beg = g_ofs[node], end = g_ofs[node + 1];

    const float4* qp = (const float4*)(g_q + (size_t)node * HID + c0);
    float4 q0 = qp[0], q1 = qp[1];

    float qw[5] = {};
    {
        float qv[8] = {q0.x, q0.y, q0.z, q0.w, q1.x, q1.y, q1.z, q1.w};
        #pragma unroll
        for (int u = 0; u < 8; u++) {
            int c = c0 + u;
            #pragma unroll
            for (int j = 0; j < 5; j++) qw[j] += qv[u] * sWe[c * 5 + j];
        }
        #pragma unroll
        for (int j = 0; j < 5; j++) {
            #pragma unroll
            for (int o = 16; o; o >>= 1) qw[j] += __shfl_xor_sync(~0u, qw[j], o);
        }
    }

    float m = -1e30f;
    float z = 0.f;
    float acc[8] = {};
    float ae0 = 0.f, ae1 = 0.f, ae2 = 0.f, ae3 = 0.f, ae4 = 0.f;

    for (int a = beg; a < end; a++) {
        int s = g_ssrc[a];
        int eid = g_seid[a];
        const float* eap = ea + (size_t)eid * 5;
        float e0 = eap[0], e1 = eap[1], e2 = eap[2], e3 = eap[3], e4 = eap[4];
        const float4* kp = (const float4*)(g_k + (size_t)s * HID + c0);
        float4 k0 = kp[0], k1 = kp[1];
        const float4* vp = (const float4*)(g_v + (size_t)s * HID + c0);
        float4 v0 = vp[0], v1 = vp[1];

        float dot = q0.x * k0.x + q0.y * k0.y + q0.z * k0.z + q0.w * k0.w
                  + q1.x * k1.x + q1.y * k1.y + q1.z * k1.z + q1.w * k1.w;
        #pragma unroll
        for (int o = 16; o; o >>= 1) dot += __shfl_xor_sync(~0u, dot, o);
        float alpha = (dot + qw[0] * e0 + qw[1] * e1 + qw[2] * e2 + qw[3] * e3 + qw[4] * e4) * 0.0625f;

        float nm = fmaxf(m, alpha);
        float sc = __expf(m - nm);
        float w  = __expf(alpha - nm);
        m = nm;
        z = z * sc + w;
        acc[0] = acc[0] * sc + w * v0.x;
        acc[1] = acc[1] * sc + w * v0.y;
        acc[2] = acc[2] * sc + w * v0.z;
        acc[3] = acc[3] * sc + w * v0.w;
        acc[4] = acc[4] * sc + w * v1.x;
        acc[5] = acc[5] * sc + w * v1.y;
        acc[6] = acc[6] * sc + w * v1.z;
        acc[7] = acc[7] * sc + w * v1.w;
        ae0 = ae0 * sc + w * e0;
        ae1 = ae1 * sc + w * e1;
        ae2 = ae2 * sc + w * e2;
        ae3 = ae3 * sc + w * e3;
        ae4 = ae4 * sc + w * e4;
    }

    float inv = 1.f / (z + 1e-16f);
    const float* skp = g_skip + (size_t)node * HID + c0;
    float* op = g_out + (size_t)node * HID + c0;
    #pragma unroll
    for (int u = 0; u < 8; u++) {
        int c = c0 + u;
        float ev = sWe[c * 5 + 0] * ae0 + sWe[c * 5 + 1] * ae1 + sWe[c * 5 + 2] * ae2
                 + sWe[c * 5 + 3] * ae3 + sWe[c * 5 + 4] * ae4;
        op[u] = (acc[u] + ev) * inv + skp[u];
    }
}

// ---------------- BN stats ----------------
__global__ __launch_bounds__(256) void k_bnstat() {
    int row0 = blockIdx.x * 32;
    int c = threadIdx.x;
    float s1 = 0.f, s2 = 0.f;
    for (int r = 0; r < 32; r++) {
        int row = row0 + r;
        if (row >= NN) break;
        float v = g_out[row * HID + c];
        s1 += v; s2 += v * v;
    }
    atomicAdd(&g_bnsum[c], s1);
    atomicAdd(&g_bnsumsq[c], s2);
}

// ---------------- BN finalize (per-block redundant) + apply + ReLU + maxpool (330 -> 18) ----------------
__global__ __launch_bounds__(256) void k_pool(const float* __restrict__ bg,
                                              const float* __restrict__ bb) {
    int bt = blockIdx.x;
    int b = bt / 18, t = bt % 18;
    int c = threadIdx.x;
    float mean = g_bnsum[c] * (1.f / NN);
    float var = g_bnsumsq[c] * (1.f / NN) - mean * mean;
    float sc = bg[c] * rsqrtf(var + 1e-5f);
    float sh = bb[c] - mean * sc;
    int base = b * 330 + t * 18;
    float mx = 0.f;
    #pragma unroll
    for (int n = 0; n < 18; n++) {
        float v = g_out[(base + n) * HID + c] * sc + sh;
        mx = fmaxf(mx, v);
    }
    g_pool[bt * HID + c] = mx;
}

// ---------------- head ----------------
__global__ __launch_bounds__(256) void k_head(const float* __restrict__ W1,
                                              const float* __restrict__ b1,
                                              const float* __restrict__ Wr) {
    __shared__ __align__(16) float row[HID];
    __shared__ float red[8];
    int bt = blockIdx.x;
    int b = bt / 18;
    int tid = threadIdx.x;
    row[tid] = g_pool[bt * HID + tid];
    __syncthreads();
    float acc = b1[tid];
    const float4* w4 = (const float4*)(W1 + tid * HID);
    const float4* r4 = (const float4*)row;
    #pragma unroll 8
    for (int j = 0; j < 64; j++) {
        float4 a = w4[j], r = r4[j];
        acc += a.x * r.x + a.y * r.y + a.z * r.z + a.w * r.w;
    }
    float h = fmaxf(acc, 0.f);
    float p = h * Wr[tid];
    #pragma unroll
    for (int o = 16; o; o >>= 1) p += __shfl_xor_sync(~0u, p, o);
    int wid = tid >> 5, lane = tid & 31;
    if (lane == 0) red[wid] = p;
    __syncthreads();
    if (tid == 0) {
        float tot = 0.f;
        #pragma unroll
        for (int i = 0; i < 8; i++) tot += red[i];
        atomicAdd(&g_bacc[b], tot);
    }
}

__global__ void k_final(const float* __restrict__ br, float* __restrict__ out) {
    int b = threadIdx.x;
    if (b < BB) {
        float c = g_bacc[b] * (1.f / 18.f) + br[0];
        out[b] = 1.f / (1.f + expf(-c));
    }
}

// ---------------- launch ----------------
extern "C" void kernel_launch(void* const* d_in, const int* in_sizes, int n_in,
                              void* d_out, int out_size) {
    const float* x   = (const float*)d_in[0];
    const int*   ei  = (const int*)  d_in[1];
    const float* ea  = (const float*)d_in[2];
    const float* Wq  = (const float*)d_in[4];
    const float* bq  = (const float*)d_in[5];
    const float* Wk  = (const float*)d_in[6];
    const float* bk  = (const float*)d_in[7];
    const float* Wv  = (const float*)d_in[8];
    const float* bv  = (const float*)d_in[9];
    const float* We  = (const float*)d_in[10];
    const float* Wsk = (const float*)d_in[11];
    const float* bsk = (const float*)d_in[12];
    const float* lg  = (const float*)d_in[13];
    const float* lb  = (const float*)d_in[14];
    const float* bg  = (const float*)d_in[15];
    const float* bb  = (const float*)d_in[16];
    const float* W1  = (const float*)d_in[17];
    const float* b1  = (const float*)d_in[18];
    const float* Wr  = (const float*)d_in[19];
    const float* br  = (const float*)d_in[20];
    float* out = (float*)d_out;

    k_init<<<128, 256>>>();
    k_count<<<(EE + 255) / 256, 256>>>(ei);
    k_scan<<<1, 1024>>>();
    k_fill<<<(EE + 255) / 256, 256>>>(ei);
    k_ln<<<NN, 128>>>(x, lg, lb);
    k_conv<<<512, 256>>>(Wq, bq, Wk, bk, Wv, bv, Wsk, bsk);
    dim3 gg(8, (NN + 63) / 64);
    k_gemm<<<gg, 128>>>(0);
    k_agg<<<(NN + 7) / 8, 256>>>(ea, We);
    k_bnstat<<<(NN + 31) / 32, 256>>>();
    k_pool<<<BB * 18, 256>>>(bg, bb);
    k_head<<<BB * 18, 256>>>(W1, b1, Wr);
    k_final<<<1, 64>>>(br, out);
}

// round 7
// speedup vs baseline: 1.6783x; 1.6783x over previous
#include <cuda_runtime.h>
#include <cuda_bf16.h>
#include <math.h>
#include <stdint.h>

#define NN 15840
#define EE 253440
#define BB 48
#define HID 256
#define INCH 128

// ---------------- scratch ----------------
__device__ __nv_bfloat16 g_xb[NN * INCH];          // LayerNormed x, bf16
__device__ __nv_bfloat16 g_wb[1024 * INCH];        // packed Wq|Wk|Wv|Wskip bf16
__device__ float g_bias[1024];
__device__ float g_q[NN * HID];
__device__ float g_k[NN * HID];
__device__ float g_v[NN * HID];
__device__ float g_skip[NN * HID];
__device__ float g_out[NN * HID];
__device__ int   g_cnt[NN];
__device__ int   g_cur[NN];
__device__ int   g_ofs[NN + 1];
__device__ int   g_ssrc[EE];
__device__ int   g_seid[EE];
__device__ float g_bnsum[HID];
__device__ float g_bnsumsq[HID];
__device__ float g_pool[BB * 18 * HID];
__device__ float g_bacc[BB];

// ---------------- init ----------------
__global__ void k_init() {
    int i = blockIdx.x * blockDim.x + threadIdx.x;
    int stride = gridDim.x * blockDim.x;
    for (int t = i; t < NN; t += stride) { g_cnt[t] = 0; g_cur[t] = 0; }
    if (i < HID) { g_bnsum[i] = 0.f; g_bnsumsq[i] = 0.f; }
    if (i < BB) g_bacc[i] = 0.f;
}

// ---------------- CSR build ----------------
__global__ __launch_bounds__(256) void k_count(const int* __restrict__ ei) {
    int e = blockIdx.x * 256 + threadIdx.x;
    if (e < EE) atomicAdd(&g_cnt[ei[EE + e]], 1);
}

__global__ __launch_bounds__(1024) void k_scan() {
    __shared__ int warpsum[32];
    int t = threadIdx.x;
    int base = t * 16;
    int loc[16];
    int s = 0;
    #pragma unroll
    for (int i = 0; i < 16; i++) {
        int idx = base + i;
        int c = (idx < NN) ? g_cnt[idx] : 0;
        loc[i] = s; s += c;
    }
    int lane = t & 31, wid = t >> 5;
    int v = s;
    #pragma unroll
    for (int o = 1; o < 32; o <<= 1) {
        int n = __shfl_up_sync(~0u, v, o);
        if (lane >= o) v += n;
    }
    if (lane == 31) warpsum[wid] = v;
    __syncthreads();
    if (wid == 0) {
        int w = warpsum[lane];
        #pragma unroll
        for (int o = 1; o < 32; o <<= 1) {
            int n = __shfl_up_sync(~0u, w, o);
            if (lane >= o) w += n;
        }
        warpsum[lane] = w;
    }
    __syncthreads();
    int offset = (v - s) + (wid ? warpsum[wid - 1] : 0);
    #pragma unroll
    for (int i = 0; i < 16; i++) {
        int idx = base + i;
        if (idx < NN) g_ofs[idx] = offset + loc[i];
    }
    if (t == 1023) g_ofs[NN] = offset + s;
}

__global__ __launch_bounds__(256) void k_fill(const int* __restrict__ ei) {
    int e = blockIdx.x * 256 + threadIdx.x;
    if (e >= EE) return;
    int d = ei[EE + e];
    int pos = atomicAdd(&g_cur[d], 1);
    int slot = g_ofs[d] + pos;
    g_ssrc[slot] = ei[e];
    g_seid[slot] = e;
}

// ---------------- LayerNorm -> bf16 ----------------
__global__ __launch_bounds__(128) void k_ln(const float* __restrict__ x,
                                            const float* __restrict__ lg,
                                            const float* __restrict__ lb) {
    int row = blockIdx.x;
    int c = threadIdx.x;
    float v = x[row * INCH + c];
    __shared__ float sm[4];
    float s = v;
    #pragma unroll
    for (int o = 16; o; o >>= 1) s += __shfl_xor_sync(~0u, s, o);
    int wid = c >> 5, lane = c & 31;
    if (lane == 0) sm[wid] = s;
    __syncthreads();
    float mean = (sm[0] + sm[1] + sm[2] + sm[3]) * (1.f / 128.f);
    float d = v - mean;
    float s2 = d * d;
    #pragma unroll
    for (int o = 16; o; o >>= 1) s2 += __shfl_xor_sync(~0u, s2, o);
    __syncthreads();
    if (lane == 0) sm[wid] = s2;
    __syncthreads();
    float var = (sm[0] + sm[1] + sm[2] + sm[3]) * (1.f / 128.f);
    g_xb[row * INCH + c] = __float2bfloat16(d * rsqrtf(var + 1e-5f) * lg[c] + lb[c]);
}

// ---------------- pack weights+bias to bf16 ----------------
__global__ __launch_bounds__(256) void k_conv(const float* __restrict__ Wq, const float* __restrict__ bq,
                                              const float* __restrict__ Wk, const float* __restrict__ bk,
                                              const float* __restrict__ Wv, const float* __restrict__ bv,
                                              const float* __restrict__ Ws, const float* __restrict__ bs) {
    int i = blockIdx.x * 256 + threadIdx.x;
    if (i < 1024 * INCH) {
        int row = i >> 7;
        int g = row >> 8, lr = row & 255, k = i & 127;
        const float* W = (g == 0) ? Wq : (g == 1) ? Wk : (g == 2) ? Wv : Ws;
        g_wb[i] = __float2bfloat16(W[lr * INCH + k]);
    }
    if (i < 1024) {
        int g = i >> 8, lr = i & 255;
        const float* b = (g == 0) ? bq : (g == 1) ? bk : (g == 2) ? bv : bs;
        g_bias[i] = b[lr];
    }
}

// ---------------- bf16 mma.sync GEMM ----------------
// grid (8, 124), 256 threads (8 warps). CTA tile: M=128 (blockIdx.y), n-group 128 weight
// rows (blockIdx.x). Whole K=128 staged in smem once. Warp tile 64x32.
// smem layout: [row][68 b32 words] -> LDS fragment reads provably bank-conflict-free.
#define ASTRIDE 68
__global__ __launch_bounds__(256) void k_gemmh() {
    extern __shared__ uint32_t sm[];
    uint32_t* As = sm;                    // 128*68 words
    uint32_t* Bs = sm + 128 * ASTRIDE;    // 128*68 words

    int tid = threadIdx.x;
    int lane = tid & 31, w = tid >> 5;
    int m0 = blockIdx.y * 128;
    int wrow0 = blockIdx.x * 128;         // weight row base 0..896
    int g = wrow0 >> 8;
    float* out = (g == 0) ? g_q : (g == 1) ? g_k : (g == 2) ? g_v : g_skip;
    int lc0 = (blockIdx.x & 1) * 128;     // col base within 256-wide output

    // fill A (128 rows x 128 bf16) and B (128 weight rows x 128 bf16)
    {
        const uint4* srcA = (const uint4*)(g_xb + (size_t)m0 * INCH);
        const uint4* srcB = (const uint4*)(g_wb + (size_t)wrow0 * INCH);
        uint4 zero = make_uint4(0u, 0u, 0u, 0u);
        #pragma unroll
        for (int it = 0; it < 8; it++) {
            int u = tid + it * 256;       // 0..2047
            int r = u >> 4, c16 = u & 15;
            uint4 va = (m0 + r < NN) ? srcA[u] : zero;
            *(uint4*)&As[r * ASTRIDE + c16 * 4] = va;
            *(uint4*)&Bs[r * ASTRIDE + c16 * 4] = srcB[u];
        }
    }
    __syncthreads();

    int mbase = (w & 1) * 64;
    int nbase = (w >> 1) * 32;
    int rl = lane >> 2, cl = lane & 3;

    float acc[4][4][4];
    #pragma unroll
    for (int mi = 0; mi < 4; mi++)
        #pragma unroll
        for (int ni = 0; ni < 4; ni++)
            #pragma unroll
            for (int r = 0; r < 4; r++) acc[mi][ni][r] = 0.f;

    #pragma unroll
    for (int ks = 0; ks < 8; ks++) {
        int kw = ks * 8;
        uint32_t b0[4], b1[4];
        #pragma unroll
        for (int ni = 0; ni < 4; ni++) {
            int n = nbase + ni * 8 + rl;
            b0[ni] = Bs[n * ASTRIDE + kw + cl];
            b1[ni] = Bs[n * ASTRIDE + kw + 4 + cl];
        }
        #pragma unroll
        for (int mi = 0; mi < 4; mi++) {
            int r = mbase + mi * 16 + rl;
            uint32_t a0 = As[r * ASTRIDE + kw + cl];
            uint32_t a1 = As[(r + 8) * ASTRIDE + kw + cl];
            uint32_t a2 = As[r * ASTRIDE + kw + 4 + cl];
            uint32_t a3 = As[(r + 8) * ASTRIDE + kw + 4 + cl];
            #pragma unroll
            for (int ni = 0; ni < 4; ni++) {
                asm volatile(
                    "mma.sync.aligned.m16n8k16.row.col.f32.bf16.bf16.f32 "
                    "{%0,%1,%2,%3}, {%4,%5,%6,%7}, {%8,%9}, {%0,%1,%2,%3};"
                    : "+f"(acc[mi][ni][0]), "+f"(acc[mi][ni][1]),
                      "+f"(acc[mi][ni][2]), "+f"(acc[mi][ni][3])
                    : "r"(a0), "r"(a1), "r"(a2), "r"(a3),
                      "r"(b0[ni]), "r"(b1[ni]));
            }
        }
    }

    // epilogue
    #pragma unroll
    for (int ni = 0; ni < 4; ni++) {
        int ncol = nbase + ni * 8 + cl * 2;
        float bb0 = g_bias[wrow0 + ncol], bb1 = g_bias[wrow0 + ncol + 1];
        int col = lc0 + ncol;
        #pragma unroll
        for (int mi = 0; mi < 4; mi++) {
            int row = m0 + mbase + mi * 16 + rl;
            if (row < NN)
                *(float2*)(out + (size_t)row * HID + col) =
                    make_float2(acc[mi][ni][0] + bb0, acc[mi][ni][1] + bb1);
            if (row + 8 < NN)
                *(float2*)(out + (size_t)(row + 8) * HID + col) =
                    make_float2(acc[mi][ni][2] + bb0, acc[mi][ni][3] + bb1);
        }
    }
}

// ---------------- fused attention: online softmax, 4-edge ILP ----------------
__global__ __launch_bounds__(256) void k_agg(const float* __restrict__ ea,
                                             const float* __restrict__ We) {
    __shared__ float sWe[HID * 5];
    for (int t = threadIdx.x; t < HID * 5; t += 256) sWe[t] = We[t];
    __syncthreads();
    int node = blockIdx.x * 8 + (threadIdx.x >> 5);
    if (node >= NN) return;
    int lane = threadIdx.x & 31;
    int c0 = lane * 8;
    int beg = g_ofs[node], end = g_ofs[node + 1];

    const float4* qp = (const float4*)(g_q + (size_t)node * HID + c0);
    float4 q0 = qp[0], q1 = qp[1];

    float qw[5] = {};
    {
        float qv[8] = {q0.x, q0.y, q0.z, q0.w, q1.x, q1.y, q1.z, q1.w};
        #pragma unroll
        for (int u = 0; u < 8; u++) {
            int c = c0 + u;
            #pragma unroll
            for (int j = 0; j < 5; j++) qw[j] += qv[u] * sWe[c * 5 + j];
        }
        #pragma unroll
        for (int j = 0; j < 5; j++) {
            #pragma unroll
            for (int o = 16; o; o >>= 1) qw[j] += __shfl_xor_sync(~0u, qw[j], o);
        }
    }

    float m = -1e30f, z = 0.f;
    float acc[8] = {};
    float ae[5] = {};

    for (int a0 = beg; a0 < end; a0 += 4) {
        int n = end - a0; if (n > 4) n = 4;
        int s[4];
        float e[4][5];
        float4 kv0[4], kv1[4], vv0[4], vv1[4];
        #pragma unroll
        for (int i = 0; i < 4; i++) {
            int idx = (i < n) ? (a0 + i) : a0;
            s[i] = g_ssrc[idx];
            int eid = g_seid[idx];
            const float* p = ea + (size_t)eid * 5;
            e[i][0] = p[0]; e[i][1] = p[1]; e[i][2] = p[2]; e[i][3] = p[3]; e[i][4] = p[4];
        }
        #pragma unroll
        for (int i = 0; i < 4; i++) {
            const float4* kp = (const float4*)(g_k + (size_t)s[i] * HID + c0);
            kv0[i] = kp[0]; kv1[i] = kp[1];
            const float4* vp = (const float4*)(g_v + (size_t)s[i] * HID + c0);
            vv0[i] = vp[0]; vv1[i] = vp[1];
        }
        float dot[4];
        #pragma unroll
        for (int i = 0; i < 4; i++) {
            dot[i] = q0.x * kv0[i].x + q0.y * kv0[i].y + q0.z * kv0[i].z + q0.w * kv0[i].w
                   + q1.x * kv1[i].x + q1.y * kv1[i].y + q1.z * kv1[i].z + q1.w * kv1[i].w;
        }
        #pragma unroll
        for (int o = 16; o; o >>= 1) {
            #pragma unroll
            for (int i = 0; i < 4; i++) dot[i] += __shfl_xor_sync(~0u, dot[i], o);
        }
        float al[4];
        #pragma unroll
        for (int i = 0; i < 4; i++) {
            al[i] = (i < n) ? (dot[i] + qw[0] * e[i][0] + qw[1] * e[i][1] + qw[2] * e[i][2]
                             + qw[3] * e[i][3] + qw[4] * e[i][4]) * 0.0625f
                            : -1e30f;
        }
        #pragma unroll
        for (int i = 0; i < 4; i++) {
            float nm = fmaxf(m, al[i]);
            float sc = __expf(m - nm);
            float w  = __expf(al[i] - nm);
            m = nm;
            z = z * sc + w;
            acc[0] = acc[0] * sc + w * vv0[i].x;
            acc[1] = acc[1] * sc + w * vv0[i].y;
            acc[2] = acc[2] * sc + w * vv0[i].z;
            acc[3] = acc[3] * sc + w * vv0[i].w;
            acc[4] = acc[4] * sc + w * vv1[i].x;
            acc[5] = acc[5] * sc + w * vv1[i].y;
            acc[6] = acc[6] * sc + w * vv1[i].z;
            acc[7] = acc[7] * sc + w * vv1[i].w;
            ae[0] = ae[0] * sc + w * e[i][0];
            ae[1] = ae[1] * sc + w * e[i][1];
            ae[2] = ae[2] * sc + w * e[i][2];
            ae[3] = ae[3] * sc + w * e[i][3];
            ae[4] = ae[4] * sc + w * e[i][4];
        }
    }

    float inv = 1.f / (z + 1e-16f);
    const float* skp = g_skip + (size_t)node * HID + c0;
    float* op = g_out + (size_t)node * HID + c0;
    #pragma unroll
    for (int u = 0; u < 8; u++) {
        int c = c0 + u;
        float ev = sWe[c * 5 + 0] * ae[0] + sWe[c * 5 + 1] * ae[1] + sWe[c * 5 + 2] * ae[2]
                 + sWe[c * 5 + 3] * ae[3] + sWe[c * 5 + 4] * ae[4];
        op[u] = (acc[u] + ev) * inv + skp[u];
    }
}

// ---------------- BN stats ----------------
__global__ __launch_bounds__(256) void k_bnstat() {
    int row0 = blockIdx.x * 32;
    int c = threadIdx.x;
    float s1 = 0.f, s2 = 0.f;
    for (int r = 0; r < 32; r++) {
        int row = row0 + r;
        if (row >= NN) break;
        float v = g_out[row * HID + c];
        s1 += v; s2 += v * v;
    }
    atomicAdd(&g_bnsum[c], s1);
    atomicAdd(&g_bnsumsq[c], s2);
}

// ---------------- BN finalize + apply + ReLU + maxpool (330 -> 18) ----------------
__global__ __launch_bounds__(256) void k_pool(const float* __restrict__ bg,
                                              const float* __restrict__ bb) {
    int bt = blockIdx.x;
    int b = bt / 18, t = bt % 18;
    int c = threadIdx.x;
    float mean = g_bnsum[c] * (1.f / NN);
    float var = g_bnsumsq[c] * (1.f / NN) - mean * mean;
    float sc = bg[c] * rsqrtf(var + 1e-5f);
    float sh = bb[c] - mean * sc;
    int base = b * 330 + t * 18;
    float mx = 0.f;
    #pragma unroll
    for (int n = 0; n < 18; n++) {
        float v = g_out[(base + n) * HID + c] * sc + sh;
        mx = fmaxf(mx, v);
    }
    g_pool[bt * HID + c] = mx;
}

// ---------------- head ----------------
__global__ __launch_bounds__(256) void k_head(const float* __restrict__ W1,
                                              const float* __restrict__ b1,
                                              const float* __restrict__ Wr) {
    __shared__ __align__(16) float row[HID];
    __shared__ float red[8];
    int bt = blockIdx.x;
    int b = bt / 18;
    int tid = threadIdx.x;
    row[tid] = g_pool[bt * HID + tid];
    __syncthreads();
    float acc = b1[tid];
    const float4* w4 = (const float4*)(W1 + tid * HID);
    const float4* r4 = (const float4*)row;
    #pragma unroll 8
    for (int j = 0; j < 64; j++) {
        float4 a = w4[j], r = r4[j];
        acc += a.x * r.x + a.y * r.y + a.z * r.z + a.w * r.w;
    }
    float h = fmaxf(acc, 0.f);
    float p = h * Wr[tid];
    #pragma unroll
    for (int o = 16; o; o >>= 1) p += __shfl_xor_sync(~0u, p, o);
    int wid = tid >> 5, lane = tid & 31;
    if (lane == 0) red[wid] = p;
    __syncthreads();
    if (tid == 0) {
        float tot = 0.f;
        #pragma unroll
        for (int i = 0; i < 8; i++) tot += red[i];
        atomicAdd(&g_bacc[b], tot);
    }
}

__global__ void k_final(const float* __restrict__ br, float* __restrict__ out) {
    int b = threadIdx.x;
    if (b < BB) {
        float c = g_bacc[b] * (1.f / 18.f) + br[0];
        out[b] = 1.f / (1.f + expf(-c));
    }
}

// ---------------- launch ----------------
extern "C" void kernel_launch(void* const* d_in, const int* in_sizes, int n_in,
                              void* d_out, int out_size) {
    const float* x   = (const float*)d_in[0];
    const int*   ei  = (const int*)  d_in[1];
    const float* ea  = (const float*)d_in[2];
    const float* Wq  = (const float*)d_in[4];
    const float* bq  = (const float*)d_in[5];
    const float* Wk  = (const float*)d_in[6];
    const float* bk  = (const float*)d_in[7];
    const float* Wv  = (const float*)d_in[8];
    const float* bv  = (const float*)d_in[9];
    const float* We  = (const float*)d_in[10];
    const float* Wsk = (const float*)d_in[11];
    const float* bsk = (const float*)d_in[12];
    const float* lg  = (const float*)d_in[13];
    const float* lb  = (const float*)d_in[14];
    const float* bg  = (const float*)d_in[15];
    const float* bb  = (const float*)d_in[16];
    const float* W1  = (const float*)d_in[17];
    const float* b1  = (const float*)d_in[18];
    const float* Wr  = (const float*)d_in[19];
    const float* br  = (const float*)d_in[20];
    float* out = (float*)d_out;

    const int GM_SMEM = 2 * 128 * ASTRIDE * 4;   // 69632 B
    static int configured = 0;
    cudaFuncSetAttribute(k_gemmh, cudaFuncAttributeMaxDynamicSharedMemorySize, GM_SMEM);
    (void)configured;

    k_init<<<128, 256>>>();
    k_count<<<(EE + 255) / 256, 256>>>(ei);
    k_scan<<<1, 1024>>>();
    k_fill<<<(EE + 255) / 256, 256>>>(ei);
    k_ln<<<NN, 128>>>(x, lg, lb);
    k_conv<<<512, 256>>>(Wq, bq, Wk, bk, Wv, bv, Wsk, bsk);
    dim3 gg(8, (NN + 127) / 128);
    k_gemmh<<<gg, 256, GM_SMEM>>>();
    k_agg<<<(NN + 7) / 8, 256>>>(ea, We);
    k_bnstat<<<(NN + 31) / 32, 256>>>();
    k_pool<<<BB * 18, 256>>>(bg, bb);
    k_head<<<BB * 18, 256>>>(W1, b1, Wr);
    k_final<<<1, 64>>>(br, out);
}

// round 8
// speedup vs baseline: 2.1023x; 1.2527x over previous
#include <cuda_runtime.h>
#include <cuda_bf16.h>
#include <math.h>
#include <stdint.h>

#define NN 15840
#define EE 253440
#define BB 48
#define HID 256
#define INCH 128

// ---------------- scratch ----------------
__device__ __nv_bfloat16 g_xb[NN * INCH];          // LayerNormed x, bf16
__device__ __nv_bfloat16 g_wb[1024 * INCH];        // packed Wq|Wk|Wv|Wskip bf16
__device__ float g_bias[1024];
__device__ float g_q[NN * HID];
__device__ __nv_bfloat16 g_kb[NN * HID];
__device__ __nv_bfloat16 g_vb[NN * HID];
__device__ float g_skip[NN * HID];
__device__ float g_out[NN * HID];
__device__ int   g_cnt[NN];        // zero at load; re-zeroed each replay by k_bnstat
__device__ int   g_cur[NN];        // ditto
__device__ int   g_ofs[NN + 1];
__device__ int   g_ssrc[EE];
__device__ int   g_seid[EE];
__device__ float g_bnsum[HID];     // re-zeroed by k_head
__device__ float g_bnsumsq[HID];   // ditto
__device__ float g_pool[BB * 18 * HID];
__device__ float g_bacc[BB];       // re-zeroed by k_final

__device__ __forceinline__ float2 bf2f2(uint32_t u) {
    __nv_bfloat162 h = *reinterpret_cast<__nv_bfloat162*>(&u);
    return __bfloat1622float2(h);
}

// ---------------- fused front: LN (warp/row) + CSR count + weight conv ----------------
#define LN_BLKS   (NN / 8)            // 1980
#define CNT_BLKS  ((EE + 255) / 256)  // 990
#define CONV_BLKS 512
__global__ __launch_bounds__(256) void k_front(const float* __restrict__ x,
                                               const float* __restrict__ lg,
                                               const float* __restrict__ lb,
                                               const int* __restrict__ ei,
                                               const float* __restrict__ Wq, const float* __restrict__ bq,
                                               const float* __restrict__ Wk, const float* __restrict__ bk,
                                               const float* __restrict__ Wv, const float* __restrict__ bv,
                                               const float* __restrict__ Ws, const float* __restrict__ bs) {
    int bid = blockIdx.x;
    if (bid < LN_BLKS) {
        int wid = threadIdx.x >> 5, lane = threadIdx.x & 31;
        int row = bid * 8 + wid;
        float4 v = ((const float4*)(x + (size_t)row * INCH))[lane];
        float s = v.x + v.y + v.z + v.w;
        #pragma unroll
        for (int o = 16; o; o >>= 1) s += __shfl_xor_sync(~0u, s, o);
        float mean = s * (1.f / 128.f);
        float dx = v.x - mean, dy = v.y - mean, dz = v.z - mean, dw = v.w - mean;
        float s2 = dx * dx + dy * dy + dz * dz + dw * dw;
        #pragma unroll
        for (int o = 16; o; o >>= 1) s2 += __shfl_xor_sync(~0u, s2, o);
        float inv = rsqrtf(s2 * (1.f / 128.f) + 1e-5f);
        float4 g4 = *(const float4*)(lg + lane * 4);
        float4 b4 = *(const float4*)(lb + lane * 4);
        __nv_bfloat162 p0 = __floats2bfloat162_rn(dx * inv * g4.x + b4.x, dy * inv * g4.y + b4.y);
        __nv_bfloat162 p1 = __floats2bfloat162_rn(dz * inv * g4.z + b4.z, dw * inv * g4.w + b4.w);
        uint2 pk;
        pk.x = *reinterpret_cast<uint32_t*>(&p0);
        pk.y = *reinterpret_cast<uint32_t*>(&p1);
        *(uint2*)(g_xb + (size_t)row * INCH + lane * 4) = pk;
    } else if (bid < LN_BLKS + CNT_BLKS) {
        int e = (bid - LN_BLKS) * 256 + threadIdx.x;
        if (e < EE) atomicAdd(&g_cnt[ei[EE + e]], 1);
    } else {
        int i = (bid - LN_BLKS - CNT_BLKS) * 256 + threadIdx.x;
        if (i < 1024 * INCH) {
            int row = i >> 7;
            int g = row >> 8, lr = row & 255, k = i & 127;
            const float* W = (g == 0) ? Wq : (g == 1) ? Wk : (g == 2) ? Wv : Ws;
            g_wb[i] = __float2bfloat16(W[lr * INCH + k]);
        }
        if (i < 1024) {
            int g = i >> 8, lr = i & 255;
            const float* b = (g == 0) ? bq : (g == 1) ? bk : (g == 2) ? bv : bs;
            g_bias[i] = b[lr];
        }
    }
}

// ---------------- CSR scan ----------------
__global__ __launch_bounds__(1024) void k_scan() {
    __shared__ int warpsum[32];
    int t = threadIdx.x;
    int base = t * 16;
    int loc[16];
    int s = 0;
    #pragma unroll
    for (int i = 0; i < 16; i++) {
        int idx = base + i;
        int c = (idx < NN) ? g_cnt[idx] : 0;
        loc[i] = s; s += c;
    }
    int lane = t & 31, wid = t >> 5;
    int v = s;
    #pragma unroll
    for (int o = 1; o < 32; o <<= 1) {
        int n = __shfl_up_sync(~0u, v, o);
        if (lane >= o) v += n;
    }
    if (lane == 31) warpsum[wid] = v;
    __syncthreads();
    if (wid == 0) {
        int w = warpsum[lane];
        #pragma unroll
        for (int o = 1; o < 32; o <<= 1) {
            int n = __shfl_up_sync(~0u, w, o);
            if (lane >= o) w += n;
        }
        warpsum[lane] = w;
    }
    __syncthreads();
    int offset = (v - s) + (wid ? warpsum[wid - 1] : 0);
    #pragma unroll
    for (int i = 0; i < 16; i++) {
        int idx = base + i;
        if (idx < NN) g_ofs[idx] = offset + loc[i];
    }
    if (t == 1023) g_ofs[NN] = offset + s;
}

__global__ __launch_bounds__(256) void k_fill(const int* __restrict__ ei) {
    int e = blockIdx.x * 256 + threadIdx.x;
    if (e >= EE) return;
    int d = ei[EE + e];
    int pos = atomicAdd(&g_cur[d], 1);
    int slot = g_ofs[d] + pos;
    g_ssrc[slot] = ei[e];
    g_seid[slot] = e;
}

// ---------------- bf16 mma.sync GEMM ----------------
#define ASTRIDE 68
__global__ __launch_bounds__(256) void k_gemmh() {
    extern __shared__ uint32_t sm[];
    uint32_t* As = sm;
    uint32_t* Bs = sm + 128 * ASTRIDE;

    int tid = threadIdx.x;
    int lane = tid & 31, w = tid >> 5;
    int m0 = blockIdx.y * 128;
    int wrow0 = blockIdx.x * 128;
    int g = wrow0 >> 8;
    int lc0 = (blockIdx.x & 1) * 128;

    {
        const uint4* srcA = (const uint4*)(g_xb + (size_t)m0 * INCH);
        const uint4* srcB = (const uint4*)(g_wb + (size_t)wrow0 * INCH);
        uint4 zero = make_uint4(0u, 0u, 0u, 0u);
        #pragma unroll
        for (int it = 0; it < 8; it++) {
            int u = tid + it * 256;
            int r = u >> 4, c16 = u & 15;
            uint4 va = (m0 + r < NN) ? srcA[u] : zero;
            *(uint4*)&As[r * ASTRIDE + c16 * 4] = va;
            *(uint4*)&Bs[r * ASTRIDE + c16 * 4] = srcB[u];
        }
    }
    __syncthreads();

    int mbase = (w & 1) * 64;
    int nbase = (w >> 1) * 32;
    int rl = lane >> 2, cl = lane & 3;

    float acc[4][4][4];
    #pragma unroll
    for (int mi = 0; mi < 4; mi++)
        #pragma unroll
        for (int ni = 0; ni < 4; ni++)
            #pragma unroll
            for (int r = 0; r < 4; r++) acc[mi][ni][r] = 0.f;

    #pragma unroll
    for (int ks = 0; ks < 8; ks++) {
        int kw = ks * 8;
        uint32_t b0[4], b1[4];
        #pragma unroll
        for (int ni = 0; ni < 4; ni++) {
            int n = nbase + ni * 8 + rl;
            b0[ni] = Bs[n * ASTRIDE + kw + cl];
            b1[ni] = Bs[n * ASTRIDE + kw + 4 + cl];
        }
        #pragma unroll
        for (int mi = 0; mi < 4; mi++) {
            int r = mbase + mi * 16 + rl;
            uint32_t a0 = As[r * ASTRIDE + kw + cl];
            uint32_t a1 = As[(r + 8) * ASTRIDE + kw + cl];
            uint32_t a2 = As[r * ASTRIDE + kw + 4 + cl];
            uint32_t a3 = As[(r + 8) * ASTRIDE + kw + 4 + cl];
            #pragma unroll
            for (int ni = 0; ni < 4; ni++) {
                asm volatile(
                    "mma.sync.aligned.m16n8k16.row.col.f32.bf16.bf16.f32 "
                    "{%0,%1,%2,%3}, {%4,%5,%6,%7}, {%8,%9}, {%0,%1,%2,%3};"
                    : "+f"(acc[mi][ni][0]), "+f"(acc[mi][ni][1]),
                      "+f"(acc[mi][ni][2]), "+f"(acc[mi][ni][3])
                    : "r"(a0), "r"(a1), "r"(a2), "r"(a3),
                      "r"(b0[ni]), "r"(b1[ni]));
            }
        }
    }

    // epilogue: g=0 -> g_q fp32, g=1 -> g_kb bf16, g=2 -> g_vb bf16, g=3 -> g_skip fp32
    bool isf32 = (g == 0) || (g == 3);
    float* outf = (g == 0) ? g_q : g_skip;
    __nv_bfloat16* outb = (g == 1) ? g_kb : g_vb;
    #pragma unroll
    for (int ni = 0; ni < 4; ni++) {
        int ncol = nbase + ni * 8 + cl * 2;
        float bb0 = g_bias[wrow0 + ncol], bb1 = g_bias[wrow0 + ncol + 1];
        int col = lc0 + ncol;
        #pragma unroll
        for (int mi = 0; mi < 4; mi++) {
            int row = m0 + mbase + mi * 16 + rl;
            float v00 = acc[mi][ni][0] + bb0, v01 = acc[mi][ni][1] + bb1;
            float v10 = acc[mi][ni][2] + bb0, v11 = acc[mi][ni][3] + bb1;
            if (isf32) {
                if (row < NN)
                    *(float2*)(outf + (size_t)row * HID + col) = make_float2(v00, v01);
                if (row + 8 < NN)
                    *(float2*)(outf + (size_t)(row + 8) * HID + col) = make_float2(v10, v11);
            } else {
                if (row < NN) {
                    __nv_bfloat162 p = __floats2bfloat162_rn(v00, v01);
                    *(uint32_t*)(outb + (size_t)row * HID + col) = *reinterpret_cast<uint32_t*>(&p);
                }
                if (row + 8 < NN) {
                    __nv_bfloat162 p = __floats2bfloat162_rn(v10, v11);
                    *(uint32_t*)(outb + (size_t)(row + 8) * HID + col) = *reinterpret_cast<uint32_t*>(&p);
                }
            }
        }
    }
}

// ---------------- fused attention: online softmax, 4-edge ILP, bf16 k/v gather ----------------
__global__ __launch_bounds__(256) void k_agg(const float* __restrict__ ea,
                                             const float* __restrict__ We) {
    __shared__ float sWe[HID * 5];
    for (int t = threadIdx.x; t < HID * 5; t += 256) sWe[t] = We[t];
    __syncthreads();
    int node = blockIdx.x * 8 + (threadIdx.x >> 5);
    if (node >= NN) return;
    int lane = threadIdx.x & 31;
    int c0 = lane * 8;
    int beg = g_ofs[node], end = g_ofs[node + 1];

    const float4* qp = (const float4*)(g_q + (size_t)node * HID + c0);
    float4 q0 = qp[0], q1 = qp[1];

    float qw[5] = {};
    {
        float qv[8] = {q0.x, q0.y, q0.z, q0.w, q1.x, q1.y, q1.z, q1.w};
        #pragma unroll
        for (int u = 0; u < 8; u++) {
            int c = c0 + u;
            #pragma unroll
            for (int j = 0; j < 5; j++) qw[j] += qv[u] * sWe[c * 5 + j];
        }
        #pragma unroll
        for (int j = 0; j < 5; j++) {
            #pragma unroll
            for (int o = 16; o; o >>= 1) qw[j] += __shfl_xor_sync(~0u, qw[j], o);
        }
    }

    float m = -1e30f, z = 0.f;
    float acc[8] = {};
    float ae[5] = {};

    for (int a0 = beg; a0 < end; a0 += 4) {
        int n = end - a0; if (n > 4) n = 4;
        int s[4];
        float e[4][5];
        uint4 kr[4], vr[4];
        #pragma unroll
        for (int i = 0; i < 4; i++) {
            int idx = (i < n) ? (a0 + i) : a0;
            s[i] = g_ssrc[idx];
            int eid = g_seid[idx];
            const float* p = ea + (size_t)eid * 5;
            e[i][0] = p[0]; e[i][1] = p[1]; e[i][2] = p[2]; e[i][3] = p[3]; e[i][4] = p[4];
        }
        #pragma unroll
        for (int i = 0; i < 4; i++) {
            kr[i] = *(const uint4*)(g_kb + (size_t)s[i] * HID + c0);
            vr[i] = *(const uint4*)(g_vb + (size_t)s[i] * HID + c0);
        }
        float dot[4];
        #pragma unroll
        for (int i = 0; i < 4; i++) {
            float2 k0 = bf2f2(kr[i].x), k1 = bf2f2(kr[i].y), k2 = bf2f2(kr[i].z), k3 = bf2f2(kr[i].w);
            dot[i] = q0.x * k0.x + q0.y * k0.y + q0.z * k1.x + q0.w * k1.y
                   + q1.x * k2.x + q1.y * k2.y + q1.z * k3.x + q1.w * k3.y;
        }
        #pragma unroll
        for (int o = 16; o; o >>= 1) {
            #pragma unroll
            for (int i = 0; i < 4; i++) dot[i] += __shfl_xor_sync(~0u, dot[i], o);
        }
        float al[4];
        #pragma unroll
        for (int i = 0; i < 4; i++) {
            al[i] = (i < n) ? (dot[i] + qw[0] * e[i][0] + qw[1] * e[i][1] + qw[2] * e[i][2]
                             + qw[3] * e[i][3] + qw[4] * e[i][4]) * 0.0625f
                            : -1e30f;
        }
        #pragma unroll
        for (int i = 0; i < 4; i++) {
            float nm = fmaxf(m, al[i]);
            float sc = __expf(m - nm);
            float w  = __expf(al[i] - nm);
            m = nm;
            z = z * sc + w;
            float2 v0 = bf2f2(vr[i].x), v1 = bf2f2(vr[i].y), v2 = bf2f2(vr[i].z), v3 = bf2f2(vr[i].w);
            acc[0] = acc[0] * sc + w * v0.x;
            acc[1] = acc[1] * sc + w * v0.y;
            acc[2] = acc[2] * sc + w * v1.x;
            acc[3] = acc[3] * sc + w * v1.y;
            acc[4] = acc[4] * sc + w * v2.x;
            acc[5] = acc[5] * sc + w * v2.y;
            acc[6] = acc[6] * sc + w * v3.x;
            acc[7] = acc[7] * sc + w * v3.y;
            ae[0] = ae[0] * sc + w * e[i][0];
            ae[1] = ae[1] * sc + w * e[i][1];
            ae[2] = ae[2] * sc + w * e[i][2];
            ae[3] = ae[3] * sc + w * e[i][3];
            ae[4] = ae[4] * sc + w * e[i][4];
        }
    }

    float inv = 1.f / (z + 1e-16f);
    const float* skp = g_skip + (size_t)node * HID + c0;
    float* op = g_out + (size_t)node * HID + c0;
    #pragma unroll
    for (int u = 0; u < 8; u++) {
        int c = c0 + u;
        float ev = sWe[c * 5 + 0] * ae[0] + sWe[c * 5 + 1] * ae[1] + sWe[c * 5 + 2] * ae[2]
                 + sWe[c * 5 + 3] * ae[3] + sWe[c * 5 + 4] * ae[4];
        op[u] = (acc[u] + ev) * inv + skp[u];
    }
}

// ---------------- BN stats (+ re-zero cnt/cur for next replay) ----------------
__global__ __launch_bounds__(256) void k_bnstat() {
    int row0 = blockIdx.x * 32;
    int c = threadIdx.x;
    float s1 = 0.f, s2 = 0.f;
    for (int r = 0; r < 32; r++) {
        int row = row0 + r;
        if (row >= NN) break;
        float v = g_out[row * HID + c];
        s1 += v; s2 += v * v;
    }
    atomicAdd(&g_bnsum[c], s1);
    atomicAdd(&g_bnsumsq[c], s2);
    int i = blockIdx.x * 256 + threadIdx.x;
    if (i < NN) { g_cnt[i] = 0; g_cur[i] = 0; }
}

// ---------------- BN finalize + apply + ReLU + maxpool (330 -> 18) ----------------
__global__ __launch_bounds__(256) void k_pool(const float* __restrict__ bg,
                                              const float* __restrict__ bb) {
    int bt = blockIdx.x;
    int b = bt / 18, t = bt % 18;
    int c = threadIdx.x;
    float mean = g_bnsum[c] * (1.f / NN);
    float var = g_bnsumsq[c] * (1.f / NN) - mean * mean;
    float sc = bg[c] * rsqrtf(var + 1e-5f);
    float sh = bb[c] - mean * sc;
    int base = b * 330 + t * 18;
    float mx = 0.f;
    #pragma unroll
    for (int n = 0; n < 18; n++) {
        float v = g_out[(base + n) * HID + c] * sc + sh;
        mx = fmaxf(mx, v);
    }
    g_pool[bt * HID + c] = mx;
}

// ---------------- head (+ re-zero bn accumulators) ----------------
__global__ __launch_bounds__(256) void k_head(const float* __restrict__ W1,
                                              const float* __restrict__ b1,
                                              const float* __restrict__ Wr) {
    __shared__ __align__(16) float row[HID];
    __shared__ float red[8];
    int bt = blockIdx.x;
    int b = bt / 18;
    int tid = threadIdx.x;
    if (bt == 0) { g_bnsum[tid] = 0.f; g_bnsumsq[tid] = 0.f; }
    row[tid] = g_pool[bt * HID + tid];
    __syncthreads();
    float acc = b1[tid];
    const float4* w4 = (const float4*)(W1 + tid * HID);
    const float4* r4 = (const float4*)row;
    #pragma unroll 8
    for (int j = 0; j < 64; j++) {
        float4 a = w4[j], r = r4[j];
        acc += a.x * r.x + a.y * r.y + a.z * r.z + a.w * r.w;
    }
    float h = fmaxf(acc, 0.f);
    float p = h * Wr[tid];
    #pragma unroll
    for (int o = 16; o; o >>= 1) p += __shfl_xor_sync(~0u, p, o);
    int wid = tid >> 5, lane = tid & 31;
    if (lane == 0) red[wid] = p;
    __syncthreads();
    if (tid == 0) {
        float tot = 0.f;
        #pragma unroll
        for (int i = 0; i < 8; i++) tot += red[i];
        atomicAdd(&g_bacc[b], tot);
    }
}

__global__ void k_final(const float* __restrict__ br, float* __restrict__ out) {
    int b = threadIdx.x;
    if (b < BB) {
        float c = g_bacc[b] * (1.f / 18.f) + br[0];
        out[b] = 1.f / (1.f + expf(-c));
        g_bacc[b] = 0.f;                  // re-zero for next replay
    }
}

// ---------------- launch ----------------
extern "C" void kernel_launch(void* const* d_in, const int* in_sizes, int n_in,
                              void* d_out, int out_size) {
    const float* x   = (const float*)d_in[0];
    const int*   ei  = (const int*)  d_in[1];
    const float* ea  = (const float*)d_in[2];
    const float* Wq  = (const float*)d_in[4];
    const float* bq  = (const float*)d_in[5];
    const float* Wk  = (const float*)d_in[6];
    const float* bk  = (const float*)d_in[7];
    const float* Wv  = (const float*)d_in[8];
    const float* bv  = (const float*)d_in[9];
    const float* We  = (const float*)d_in[10];
    const float* Wsk = (const float*)d_in[11];
    const float* bsk = (const float*)d_in[12];
    const float* lg  = (const float*)d_in[13];
    const float* lb  = (const float*)d_in[14];
    const float* bg  = (const float*)d_in[15];
    const float* bb  = (const float*)d_in[16];
    const float* W1  = (const float*)d_in[17];
    const float* b1  = (const float*)d_in[18];
    const float* Wr  = (const float*)d_in[19];
    const float* br  = (const float*)d_in[20];
    float* out = (float*)d_out;

    const int GM_SMEM = 2 * 128 * ASTRIDE * 4;   // 69632 B
    cudaFuncSetAttribute(k_gemmh, cudaFuncAttributeMaxDynamicSharedMemorySize, GM_SMEM);

    k_front<<<LN_BLKS + CNT_BLKS + CONV_BLKS, 256>>>(x, lg, lb, ei,
                                                     Wq, bq, Wk, bk, Wv, bv, Wsk, bsk);
    k_scan<<<1, 1024>>>();
    k_fill<<<(EE + 255) / 256, 256>>>(ei);
    dim3 gg(8, (NN + 127) / 128);
    k_gemmh<<<gg, 256, GM_SMEM>>>();
    k_agg<<<(NN + 7) / 8, 256>>>(ea, We);
    k_bnstat<<<(NN + 31) / 32, 256>>>();
    k_pool<<<BB * 18, 256>>>(bg, bb);
    k_head<<<BB * 18, 256>>>(W1, b1, Wr);
    k_final<<<1, 64>>>(br, out);
}